// round 8
// baseline (speedup 1.0000x reference)
#include <cuda_runtime.h>

#define C 512
#define SEGS 49          // 50176 float4 per channel = 49 tiles of 1024 float4
#define SEGLEN 1024      // float4 per tile (16 KB); 512 threads x 2 float4
#define FULLMASK 0xffffffffu

// ---- scratch (no allocs allowed) -------------------------------------------
__device__ float g_part[C][SEGS];       // per-tile partial sums (fast path)
__device__ float g_part8[C][8];         // fallback partials
__device__ float g_bv[C];
__device__ float g_xtmp[C];
__device__ float g_xsparse[C];
__device__ float g_scale[C];
__device__ float g_coeff;
__device__ unsigned g_cnt = 0;          // monotonic barrier ticket (never reset)
__device__ volatile unsigned g_rel = 0; // monotonic release watermark
__device__ unsigned g_ctr2 = 0;         // fallback last-block counter

// ---- software grid barrier (all blocks resident; monotonic, replay-safe) ----
__device__ __forceinline__ void gbar(unsigned nblk) {
    __syncthreads();
    if (threadIdx.x == 0) {
        __threadfence();
        unsigned t = atomicAdd(&g_cnt, 1u) + 1u;
        unsigned target = ((t + nblk - 1u) / nblk) * nblk;   // ceil to multiple
        if (t == target) {
            g_rel = target;
            __threadfence();
        } else {
            while (g_rel < target) { __nanosleep(64); }
            __threadfence();
        }
    }
    __syncthreads();
}

// ---- 512-thread (16-warp) block reductions -----------------------------------
__device__ __forceinline__ float bsum(float v, volatile float* sm) {
    #pragma unroll
    for (int o = 16; o; o >>= 1) v += __shfl_xor_sync(FULLMASK, v, o);
    const int lane = threadIdx.x & 31, w = threadIdx.x >> 5;
    if (lane == 0) sm[w] = v;
    __syncthreads();
    if (threadIdx.x < 32) {
        v = (lane < 16) ? sm[lane] : 0.f;
        #pragma unroll
        for (int o = 8; o; o >>= 1) v += __shfl_xor_sync(FULLMASK, v, o);
        if (lane == 0) sm[0] = v;
    }
    __syncthreads();
    float r = sm[0];
    __syncthreads();
    return r;
}

__device__ __forceinline__ float bmax(float v, volatile float* sm) {
    #pragma unroll
    for (int o = 16; o; o >>= 1) v = fmaxf(v, __shfl_xor_sync(FULLMASK, v, o));
    const int lane = threadIdx.x & 31, w = threadIdx.x >> 5;
    if (lane == 0) sm[w] = v;
    __syncthreads();
    if (threadIdx.x < 32) {
        v = (lane < 16) ? sm[lane] : -3.4e38f;
        #pragma unroll
        for (int o = 8; o; o >>= 1) v = fmaxf(v, __shfl_xor_sync(FULLMASK, v, o));
        if (lane == 0) sm[0] = v;
    }
    __syncthreads();
    float r = sm[0];
    __syncthreads();
    return r;
}

// ================= fast path: one persistent kernel ===========================
__global__ void __launch_bounds__(512)
k_fused(const float* __restrict__ x, const float* __restrict__ W,
        float* __restrict__ out, const float* __restrict__ bw,
        float* __restrict__ bwout, float inv_hw, int nblk) {
    const int tid = threadIdx.x;
    const int bid = blockIdx.x;
    const float4* x4 = reinterpret_cast<const float4*>(x);
    __shared__ float av[C];
    __shared__ float sm[16];

    // ---- phase 1: per-tile channel sums (deterministic, one writer per tile)
    const int NT = C * SEGS;
    for (int t = bid; t < NT; t += nblk) {
        const int c = t / SEGS;
        const int k = t - c * SEGS;
        const float4* p = x4 + (size_t)c * (SEGS * SEGLEN) + (size_t)k * SEGLEN;
        float4 a = __ldcs(p + tid);
        float4 b = __ldcs(p + tid + 512);
        float s = ((a.x + a.y) + (a.z + a.w)) + ((b.x + b.y) + (b.z + b.w));
        #pragma unroll
        for (int o = 16; o; o >>= 1) s += __shfl_xor_sync(FULLMASK, s, o);
        if ((tid & 31) == 0) sm[tid >> 5] = s;
        __syncthreads();
        if (tid == 0) {
            float r = 0.f;
            #pragma unroll
            for (int i = 0; i < 16; i++) r += sm[i];
            g_part[c][k] = r;
        }
        __syncthreads();
    }

    gbar(nblk);

    // ---- block 0: matvec (1 row/thread) + stats ----------------------------
    if (bid == 0) {
        float s49 = 0.f;
        #pragma unroll
        for (int k = 0; k < SEGS; k++) s49 += g_part[tid][k];
        const float a = s49 * inv_hw;
        av[tid] = a;
        __syncthreads();

        const float4* w4 = reinterpret_cast<const float4*>(W) + (size_t)tid * (C / 4);
        float acc = 0.f;
        #pragma unroll 4
        for (int j = 0; j < C / 4; j++) {
            float4 w = __ldg(w4 + j);
            acc += w.x * av[4*j] + w.y * av[4*j+1] + w.z * av[4*j+2] + w.w * av[4*j+3];
        }

        const float inh = bsum(acc, sm) * (1.0f / (float)C);
        float xt = a + acc - 2.0f * inh;
        xt = xt > 0.f ? xt : 0.f;
        const float thr = bmax(xt, sm) * 0.9f;
        const float xs = (xt < thr) ? 0.f : xt;
        g_xtmp[tid]    = xt;
        g_xsparse[tid] = xs;
        g_scale[tid]   = xt / (a + 1e-12f);

        const float st2 = bsum(xt * xt, sm);
        const float ss2 = bsum(xs * xs, sm);
        const float ts  = xt * xs;
        const float sd2 = bsum(ts * ts, sm);
        if (tid == 0) {
            const float n2 = st2 * ss2 - sd2;
            const float n  = sqrtf(n2);
            float cf = 0.05f;
            if (isfinite(n) && n > 0.f) cf = 0.05f / n;
            g_coeff = cf;
        }
    }

    gbar(nblk);

    // ---- phase 2a: boost-weight (128 tiles of 512 float4, done first/hidden)
    if (bwout) {
        const float coeff = g_coeff;
        const float4* bw4 = reinterpret_cast<const float4*>(bw);
        float4* bo4 = reinterpret_cast<float4*>(bwout);
        for (int t = bid; t < 128; t += nblk) {
            const int j4   = t * 512 + tid;
            const int row  = j4 >> 7;
            const int col0 = (j4 & 127) << 2;
            float4 w = __ldg(bw4 + j4);
            const float xv = g_xtmp[row];
            float4 r;
            r.x = w.x * 0.5f + ((row == col0    ) ? 0.f : coeff * xv * g_xsparse[col0]);
            r.y = w.y * 0.5f + ((row == col0 + 1) ? 0.f : coeff * xv * g_xsparse[col0 + 1]);
            r.z = w.z * 0.5f + ((row == col0 + 2) ? 0.f : coeff * xv * g_xsparse[col0 + 2]);
            r.w = w.w * 0.5f + ((row == col0 + 3) ? 0.f : coeff * xv * g_xsparse[col0 + 3]);
            bo4[j4] = r;
        }
    }

    // ---- phase 2b: out = x * scale[c], streaming ----------------------------
    float4* o4 = reinterpret_cast<float4*>(out);
    #pragma unroll 2
    for (int t = bid; t < NT; t += nblk) {
        const int c = t / SEGS;
        const int k = t - c * SEGS;
        const size_t base = (size_t)c * (SEGS * SEGLEN) + (size_t)k * SEGLEN;
        const float sc = g_scale[c];
        float4 a = __ldcs(x4 + base + tid);
        float4 b = __ldcs(x4 + base + tid + 512);
        a.x *= sc; a.y *= sc; a.z *= sc; a.w *= sc;
        b.x *= sc; b.y *= sc; b.z *= sc; b.w *= sc;
        __stcs(o4 + base + tid, a);
        __stcs(o4 + base + tid + 512, b);
    }
}

// ================= generic fallback path (any shape) ==========================
__global__ void fb_mean(const float* __restrict__ x, int n4, int seglen, int nseg) {
    const int c = blockIdx.y, seg = blockIdx.x;
    const float4* xp = reinterpret_cast<const float4*>(x) + (size_t)c * n4 + (size_t)seg * seglen;
    const int lim = min(seglen, n4 - seg * seglen);
    float s = 0.f;
    for (int i = threadIdx.x; i < lim; i += blockDim.x) {
        float4 v = __ldcs(xp + i);
        s += (v.x + v.y) + (v.z + v.w);
    }
    __shared__ float sm[8];
    #pragma unroll
    for (int o = 16; o; o >>= 1) s += __shfl_xor_sync(FULLMASK, s, o);
    const int lane = threadIdx.x & 31, w = threadIdx.x >> 5;
    if (lane == 0) sm[w] = s;
    __syncthreads();
    if (threadIdx.x == 0) {
        float t = 0.f;
        for (int k = 0; k < (int)(blockDim.x >> 5); k++) t += sm[k];
        g_part8[c][seg] = t;
    }
}

__global__ void fb_matvec_stats(const float* __restrict__ W, float inv_hw, int nseg) {
    __shared__ float av[C];
    __shared__ float sm[16];
    __shared__ int   is_last;
    const int t = threadIdx.x;  // 512 threads
    {
        float s = 0.f;
        for (int k = 0; k < nseg; k++) s += g_part8[t][k];
        av[t] = s * inv_hw;
    }
    __syncthreads();
    const int row = blockIdx.x;
    {
        const float4* w4 = reinterpret_cast<const float4*>(W) + (size_t)row * (C / 4);
        float partial = 0.f;
        for (int j = t; j < C / 4; j += 512) {
            float4 w = __ldg(w4 + j);
            partial += w.x * av[4*j] + w.y * av[4*j+1] + w.z * av[4*j+2] + w.w * av[4*j+3];
        }
        float tot = bsum(partial, sm);
        if (t == 0) {
            g_bv[row] = tot;
            __threadfence();
            unsigned old = atomicAdd(&g_ctr2, 1u);
            is_last = ((old & (C - 1)) == (C - 1)) ? 1 : 0;
        }
    }
    __syncthreads();
    if (!is_last) return;
    __threadfence();
    const float a = av[t];
    const float b = g_bv[t];
    const float inh = bsum(b, sm) * (1.0f / (float)C);
    float xt = a + b - 2.0f * inh;
    xt = xt > 0.f ? xt : 0.f;
    const float thr = bmax(xt, sm) * 0.9f;
    const float xs = (xt < thr) ? 0.f : xt;
    g_xtmp[t] = xt; g_xsparse[t] = xs; g_scale[t] = xt / (a + 1e-12f);
    const float st2 = bsum(xt * xt, sm);
    const float ss2 = bsum(xs * xs, sm);
    const float ts  = xt * xs;
    const float sd2 = bsum(ts * ts, sm);
    if (t == 0) {
        const float n2 = st2 * ss2 - sd2;
        const float n  = sqrtf(n2);
        float cf = 0.05f;
        if (isfinite(n) && n > 0.f) cf = 0.05f / n;
        g_coeff = cf;
    }
}

__global__ void fb_apply(const float* __restrict__ x, float* __restrict__ out, int hw,
                         const float* __restrict__ bw, float* __restrict__ bwout) {
    if (blockIdx.y == 0) {
        if (bwout) {
            const float coeff = g_coeff;
            const int stride = gridDim.x * 256;
            for (int j = blockIdx.x * 256 + threadIdx.x; j < C * C; j += stride) {
                const int i = j >> 9, col = j & (C - 1);
                const float wt = (i == col) ? 0.f : g_xtmp[i] * g_xsparse[col];
                bwout[j] = bw[j] * 0.5f + coeff * wt;
            }
        }
        return;
    }
    const int c = blockIdx.y - 1;
    const float sc = g_scale[c];
    const size_t base = (size_t)c * hw;
    for (int i = blockIdx.x * 256 + threadIdx.x; i < hw; i += gridDim.x * 256)
        out[base + i] = x[base + i] * sc;
}

// ---- launch -------------------------------------------------------------------
extern "C" void kernel_launch(void* const* d_in, const int* in_sizes, int n_in,
                              void* d_out, int out_size) {
    int xi = 0, bi = 1;
    if (n_in >= 2 && in_sizes[0] < in_sizes[1]) { xi = 1; bi = 0; }
    const float* x  = (const float*)d_in[xi];
    const float* bw = (const float*)d_in[bi];
    float* out = (float*)d_out;

    const int n0 = in_sizes[xi];        // 512 * 448 * 448
    const int hw = n0 / C;              // 200704
    const int hw4 = hw >> 2;            // 50176 = 49 * 1024
    const float inv_hw = 1.0f / (float)hw;
    float* bwout = (out_size >= n0 + C * C) ? (out + n0) : nullptr;

    if ((hw & 3) == 0 && hw4 == SEGS * SEGLEN) {
        // fast path: persistent fused kernel, all blocks resident
        int dev = 0, nsm = 0, occ = 0;
        cudaGetDevice(&dev);
        cudaDeviceGetAttribute(&nsm, cudaDevAttrMultiProcessorCount, dev);
        cudaOccupancyMaxActiveBlocksPerMultiprocessor(&occ, k_fused, 512, 0);
        if (occ < 1) occ = 1;
        int nblk = nsm * occ;
        const int NT = C * SEGS;
        if (nblk > NT) nblk = NT;
        k_fused<<<nblk, 512>>>(x, bw, out, bw, bwout, inv_hw, nblk);
    } else {
        // generic fallback
        const int nseg = 8;
        const int n4 = hw4;
        const int seglen = (n4 + nseg - 1) / nseg;
        dim3 gmean(nseg, C);
        fb_mean<<<gmean, 256>>>(x, n4, seglen, nseg);
        fb_matvec_stats<<<C, 512>>>(bw, inv_hw, nseg);
        dim3 gapply(128, C + 1);
        fb_apply<<<gapply, 256>>>(x, out, hw, bw, bwout);
    }
}

// round 9
// speedup vs baseline: 1.0094x; 1.0094x over previous
#include <cuda_runtime.h>

#define C 512
#define NSEG 7          // 50176/7 = 7168 = 7*1024 -> guard-free fast path
#define FULLMASK 0xffffffffu

// ---- scratch (no allocs allowed) -------------------------------------------
__device__ float g_part[C][NSEG];       // fast-path partials
__device__ float g_part8[C][8];         // fallback partials
__device__ float g_bv[C];
__device__ float g_xtmp[C];
__device__ float g_xsparse[C];
__device__ float g_scale[C];
__device__ float g_coeff;
__device__ unsigned g_ctr  = 0;         // fast-path ticket (monotonic, replay-safe)
__device__ unsigned g_ctr2 = 0;         // fallback ticket

// ---- reductions over 1024 threads (32 warps), others contribute identity ----
__device__ __forceinline__ float bsum1024(float v, volatile float* sm) {
    #pragma unroll
    for (int o = 16; o; o >>= 1) v += __shfl_xor_sync(FULLMASK, v, o);
    const int lane = threadIdx.x & 31, w = threadIdx.x >> 5;
    if (lane == 0) sm[w] = v;
    __syncthreads();
    if (threadIdx.x < 32) {
        v = sm[lane];
        #pragma unroll
        for (int o = 16; o; o >>= 1) v += __shfl_xor_sync(FULLMASK, v, o);
        if (lane == 0) sm[0] = v;
    }
    __syncthreads();
    float r = sm[0];
    __syncthreads();
    return r;
}

__device__ __forceinline__ float bmax1024(float v, volatile float* sm) {
    #pragma unroll
    for (int o = 16; o; o >>= 1) v = fmaxf(v, __shfl_xor_sync(FULLMASK, v, o));
    const int lane = threadIdx.x & 31, w = threadIdx.x >> 5;
    if (lane == 0) sm[w] = v;
    __syncthreads();
    if (threadIdx.x < 32) {
        v = sm[lane];
        #pragma unroll
        for (int o = 16; o; o >>= 1) v = fmaxf(v, __shfl_xor_sync(FULLMASK, v, o));
        if (lane == 0) sm[0] = v;
    }
    __syncthreads();
    float r = sm[0];
    __syncthreads();
    return r;
}

// ---- K1 (fast): mean partials + last-block matvec/stats; PDL trigger early ----
__global__ void __launch_bounds__(1024)
k_mean_stats(const float* __restrict__ x, const float* __restrict__ W,
             float inv_hw, int n4, int seglen, unsigned nblk) {
    const int c   = blockIdx.y;
    const int seg = blockIdx.x;
    const float4* xp = reinterpret_cast<const float4*>(x) + (size_t)c * n4 + (size_t)seg * seglen;

    // seglen == 7168 == 7*1024, blockDim == 1024: fully front-batched
    const int t = threadIdx.x;
    float4 v0 = __ldcs(xp + t);
    float4 v1 = __ldcs(xp + t + 1024);
    float4 v2 = __ldcs(xp + t + 2048);
    float4 v3 = __ldcs(xp + t + 3072);
    float4 v4 = __ldcs(xp + t + 4096);
    float4 v5 = __ldcs(xp + t + 5120);
    float4 v6 = __ldcs(xp + t + 6144);
    float a0 = (v0.x + v0.y) + (v0.z + v0.w);
    float a1 = (v1.x + v1.y) + (v1.z + v1.w);
    float a2 = (v2.x + v2.y) + (v2.z + v2.w);
    float a3 = (v3.x + v3.y) + (v3.z + v3.w);
    float a4 = (v4.x + v4.y) + (v4.z + v4.w);
    float a5 = (v5.x + v5.y) + (v5.z + v5.w);
    float a6 = (v6.x + v6.y) + (v6.z + v6.w);
    float s = ((a0 + a1) + (a2 + a3)) + ((a4 + a5) + a6);

    __shared__ float sm[32];
    __shared__ float av[C];
    __shared__ int   is_last;

    #pragma unroll
    for (int o = 16; o; o >>= 1) s += __shfl_xor_sync(FULLMASK, s, o);
    const int lane = t & 31, w = t >> 5;
    if (lane == 0) sm[w] = s;
    __syncthreads();
    if (t == 0) {
        float r = 0.f;
        #pragma unroll
        for (int k = 0; k < 32; k++) r += sm[k];
        g_part[c][seg] = r;
        __threadfence();
        unsigned old = atomicAdd(&g_ctr, 1u);
        is_last = ((old % nblk) == nblk - 1u) ? 1 : 0;
    }

#if __CUDA_ARCH__ >= 900
    // allow the dependent apply kernel to start scheduling as this grid drains
    cudaTriggerProgrammaticLaunchCompletion();
#endif

    __syncthreads();
    if (!is_last) return;

    // ---- matvec + stats in the single last-finishing block ----
    __threadfence();
    float a = 0.f, b = 0.f;
    if (t < C) {
        float s49 = 0.f;
        #pragma unroll
        for (int k = 0; k < NSEG; k++) s49 += g_part[t][k];
        a = s49 * inv_hw;
        av[t] = a;
    }
    __syncthreads();
    if (t < C) {
        const float4* w4 = reinterpret_cast<const float4*>(W) + (size_t)t * (C / 4);
        float acc = 0.f;
        #pragma unroll 4
        for (int j = 0; j < C / 4; j++) {
            float4 wv = __ldg(w4 + j);
            acc += wv.x * av[4*j] + wv.y * av[4*j+1] + wv.z * av[4*j+2] + wv.w * av[4*j+3];
        }
        b = acc;
    }

    const float inh = bsum1024((t < C) ? b : 0.f, sm) * (1.0f / (float)C);
    float xt = 0.f, xs = 0.f;
    if (t < C) {
        xt = a + b - 2.0f * inh;
        xt = xt > 0.f ? xt : 0.f;
    }
    const float thr = bmax1024((t < C) ? xt : -3.4e38f, sm) * 0.9f;
    if (t < C) {
        xs = (xt < thr) ? 0.f : xt;
        g_xtmp[t]    = xt;
        g_xsparse[t] = xs;
        g_scale[t]   = xt / (a + 1e-12f);
    }
    const float st2 = bsum1024(xt * xt, sm);
    const float ss2 = bsum1024(xs * xs, sm);
    const float ts  = xt * xs;
    const float sd2 = bsum1024(ts * ts, sm);
    if (t == 0) {
        const float n2 = st2 * ss2 - sd2;
        const float n  = sqrtf(n2);
        float cf = 0.05f;
        if (isfinite(n) && n > 0.f) cf = 0.05f / n;
        g_coeff = cf;
    }
}

// ---- K2 (fast): apply + bw plane; waits on PDL dependency --------------------
__global__ void __launch_bounds__(256)
k_apply(const float* __restrict__ x, float* __restrict__ out, int hw4,
        const float* __restrict__ bw, float* __restrict__ bwout) {
#if __CUDA_ARCH__ >= 900
    cudaGridDependencySynchronize();
#endif
    if (blockIdx.y == 0) {
        if (bwout) {
            const float coeff = g_coeff;
            const int n4 = (C * C) / 4;                 // 65536 float4
            const int stride = gridDim.x * 256;
            const float4* bw4 = reinterpret_cast<const float4*>(bw);
            float4* bo4 = reinterpret_cast<float4*>(bwout);
            for (int j4 = blockIdx.x * 256 + threadIdx.x; j4 < n4; j4 += stride) {
                const int row  = j4 >> 7;
                const int col0 = (j4 & 127) << 2;
                float4 w = __ldg(bw4 + j4);
                const float xv = g_xtmp[row];
                float4 r;
                r.x = w.x * 0.5f + ((row == col0    ) ? 0.f : coeff * xv * g_xsparse[col0]);
                r.y = w.y * 0.5f + ((row == col0 + 1) ? 0.f : coeff * xv * g_xsparse[col0 + 1]);
                r.z = w.z * 0.5f + ((row == col0 + 2) ? 0.f : coeff * xv * g_xsparse[col0 + 2]);
                r.w = w.w * 0.5f + ((row == col0 + 3) ? 0.f : coeff * xv * g_xsparse[col0 + 3]);
                bo4[j4] = r;
            }
        }
        return;
    }

    const int c = blockIdx.y - 1;
    const float sc = g_scale[c];
    const size_t base = (size_t)c * hw4;
    const float4* xp = reinterpret_cast<const float4*>(x) + base;
    float4*       op = reinterpret_cast<float4*>(out) + base;

    const int i0 = blockIdx.x * 1024 + threadIdx.x;
    const int i1 = i0 + 256, i2 = i0 + 512, i3 = i0 + 768;

    float4 v0 = __ldcs(xp + i0);
    float4 v1 = __ldcs(xp + i1);
    float4 v2 = __ldcs(xp + i2);
    float4 v3 = __ldcs(xp + i3);
    v0.x *= sc; v0.y *= sc; v0.z *= sc; v0.w *= sc; __stcs(op + i0, v0);
    v1.x *= sc; v1.y *= sc; v1.z *= sc; v1.w *= sc; __stcs(op + i1, v1);
    v2.x *= sc; v2.y *= sc; v2.z *= sc; v2.w *= sc; __stcs(op + i2, v2);
    v3.x *= sc; v3.y *= sc; v3.z *= sc; v3.w *= sc; __stcs(op + i3, v3);
}

// ================= generic fallback path (any shape) ==========================
__global__ void fb_mean(const float* __restrict__ x, int n4, int seglen, int nseg) {
    const int c = blockIdx.y, seg = blockIdx.x;
    const float4* xp = reinterpret_cast<const float4*>(x) + (size_t)c * n4 + (size_t)seg * seglen;
    const int lim = min(seglen, n4 - seg * seglen);
    float s = 0.f;
    for (int i = threadIdx.x; i < lim; i += blockDim.x) {
        float4 v = __ldcs(xp + i);
        s += (v.x + v.y) + (v.z + v.w);
    }
    __shared__ float sm[8];
    #pragma unroll
    for (int o = 16; o; o >>= 1) s += __shfl_xor_sync(FULLMASK, s, o);
    const int lane = threadIdx.x & 31, w = threadIdx.x >> 5;
    if (lane == 0) sm[w] = s;
    __syncthreads();
    if (threadIdx.x == 0) {
        float t = 0.f;
        for (int k = 0; k < (int)(blockDim.x >> 5); k++) t += sm[k];
        g_part8[c][seg] = t;
    }
}

__device__ __forceinline__ float bsum512(float v, volatile float* sm) {
    #pragma unroll
    for (int o = 16; o; o >>= 1) v += __shfl_xor_sync(FULLMASK, v, o);
    const int lane = threadIdx.x & 31, w = threadIdx.x >> 5;
    if (lane == 0) sm[w] = v;
    __syncthreads();
    if (threadIdx.x < 32) {
        v = (lane < 16) ? sm[lane] : 0.f;
        #pragma unroll
        for (int o = 8; o; o >>= 1) v += __shfl_xor_sync(FULLMASK, v, o);
        if (lane == 0) sm[0] = v;
    }
    __syncthreads();
    float r = sm[0];
    __syncthreads();
    return r;
}

__device__ __forceinline__ float bmax512(float v, volatile float* sm) {
    #pragma unroll
    for (int o = 16; o; o >>= 1) v = fmaxf(v, __shfl_xor_sync(FULLMASK, v, o));
    const int lane = threadIdx.x & 31, w = threadIdx.x >> 5;
    if (lane == 0) sm[w] = v;
    __syncthreads();
    if (threadIdx.x < 32) {
        v = (lane < 16) ? sm[lane] : -3.4e38f;
        #pragma unroll
        for (int o = 8; o; o >>= 1) v = fmaxf(v, __shfl_xor_sync(FULLMASK, v, o));
        if (lane == 0) sm[0] = v;
    }
    __syncthreads();
    float r = sm[0];
    __syncthreads();
    return r;
}

__global__ void fb_matvec_stats(const float* __restrict__ W, float inv_hw, int nseg) {
    __shared__ float av[C];
    __shared__ float sm[16];
    __shared__ int   is_last;
    const int t = threadIdx.x;  // 512 threads
    {
        float s = 0.f;
        for (int k = 0; k < nseg; k++) s += g_part8[t][k];
        av[t] = s * inv_hw;
    }
    __syncthreads();
    const int row = blockIdx.x;
    {
        const float4* w4 = reinterpret_cast<const float4*>(W) + (size_t)row * (C / 4);
        float partial = 0.f;
        for (int j = t; j < C / 4; j += 512) {
            float4 w = __ldg(w4 + j);
            partial += w.x * av[4*j] + w.y * av[4*j+1] + w.z * av[4*j+2] + w.w * av[4*j+3];
        }
        float tot = bsum512(partial, sm);
        if (t == 0) {
            g_bv[row] = tot;
            __threadfence();
            unsigned old = atomicAdd(&g_ctr2, 1u);
            is_last = ((old & (C - 1)) == (C - 1)) ? 1 : 0;
        }
    }
    __syncthreads();
    if (!is_last) return;
    __threadfence();
    const float a = av[t];
    const float b = g_bv[t];
    const float inh = bsum512(b, sm) * (1.0f / (float)C);
    float xt = a + b - 2.0f * inh;
    xt = xt > 0.f ? xt : 0.f;
    const float thr = bmax512(xt, sm) * 0.9f;
    const float xs = (xt < thr) ? 0.f : xt;
    g_xtmp[t] = xt; g_xsparse[t] = xs; g_scale[t] = xt / (a + 1e-12f);
    const float st2 = bsum512(xt * xt, sm);
    const float ss2 = bsum512(xs * xs, sm);
    const float ts  = xt * xs;
    const float sd2 = bsum512(ts * ts, sm);
    if (t == 0) {
        const float n2 = st2 * ss2 - sd2;
        const float n  = sqrtf(n2);
        float cf = 0.05f;
        if (isfinite(n) && n > 0.f) cf = 0.05f / n;
        g_coeff = cf;
    }
}

__global__ void fb_apply(const float* __restrict__ x, float* __restrict__ out, int hw,
                         const float* __restrict__ bw, float* __restrict__ bwout) {
    if (blockIdx.y == 0) {
        if (bwout) {
            const float coeff = g_coeff;
            const int stride = gridDim.x * 256;
            for (int j = blockIdx.x * 256 + threadIdx.x; j < C * C; j += stride) {
                const int i = j >> 9, col = j & (C - 1);
                const float wt = (i == col) ? 0.f : g_xtmp[i] * g_xsparse[col];
                bwout[j] = bw[j] * 0.5f + coeff * wt;
            }
        }
        return;
    }
    const int c = blockIdx.y - 1;
    const float sc = g_scale[c];
    const size_t base = (size_t)c * hw;
    for (int i = blockIdx.x * 256 + threadIdx.x; i < hw; i += gridDim.x * 256)
        out[base + i] = x[base + i] * sc;
}

// ---- launch -------------------------------------------------------------------
extern "C" void kernel_launch(void* const* d_in, const int* in_sizes, int n_in,
                              void* d_out, int out_size) {
    int xi = 0, bi = 1;
    if (n_in >= 2 && in_sizes[0] < in_sizes[1]) { xi = 1; bi = 0; }
    const float* x  = (const float*)d_in[xi];
    const float* bw = (const float*)d_in[bi];
    float* out = (float*)d_out;

    const int n0 = in_sizes[xi];        // 512 * 448 * 448
    const int hw = n0 / C;              // 200704
    const int hw4 = hw >> 2;            // 50176 = 49*1024
    const float inv_hw = 1.0f / (float)hw;
    float* bwout = (out_size >= n0 + C * C) ? (out + n0) : nullptr;

    if ((hw & 3) == 0 && hw4 % (NSEG * 1024) == 0 && hw4 % 1024 == 0) {
        const int seglen = hw4 / NSEG;
        const unsigned nblk = NSEG * C;

        // A: mean + fused matvec/stats
        k_mean_stats<<<dim3(NSEG, C), 1024>>>(x, bw, inv_hw, hw4, seglen, nblk);

        // B: apply + bw, PDL-serialized so its ramp overlaps A's drain
        {
            cudaLaunchConfig_t cfg = {};
            cfg.gridDim  = dim3(hw4 / 1024, C + 1, 1);
            cfg.blockDim = dim3(256, 1, 1);
            cudaLaunchAttribute attr[1];
            attr[0].id = cudaLaunchAttributeProgrammaticStreamSerialization;
            attr[0].val.programmaticStreamSerializationAllowed = 1;
            cfg.attrs = attr;
            cfg.numAttrs = 1;
            cudaLaunchKernelEx(&cfg, k_apply, x, out, hw4, (const float*)bw, bwout);
        }
    } else {
        // generic fallback
        const int nseg = 8;
        const int seglen = (hw4 + nseg - 1) / nseg;
        fb_mean<<<dim3(nseg, C), 256>>>(x, hw4, seglen, nseg);
        fb_matvec_stats<<<C, 512>>>(bw, inv_hw, nseg);
        fb_apply<<<dim3(128, C + 1), 256>>>(x, out, hw, bw, bwout);
    }
}